// round 1
// baseline (speedup 1.0000x reference)
#include <cuda_runtime.h>
#include <math.h>

// Problem dims
#define Bb   1024
#define Ss   50
#define Ll   200
#define Ff   4
#define Ee   32
#define Dd   128     // F*E
#define UEe  256     // U*E
#define NEGV -1000000000.0f

// ---------------- scratch (static __device__, no allocation) ----------------
__device__ float d_st0[Bb*Ss*Dd];     // embedded short-term
__device__ float d_X  [Bb*Ss*4*Dd];   // precomputed x@W + b  (B,S,512)
__device__ float d_hs [Bb*Ss*Dd];     // lstm outputs
__device__ float d_q  [Bb*Ss*Dd];
__device__ float d_k  [Bb*Ss*Dd];
__device__ float d_v  [Bb*Ss*Dd];
__device__ float d_ao [Bb*Ss*Dd];     // attention out (pre-Wo)
__device__ float d_stm[Bb*Ss*Dd];     // mha output
__device__ float d_ue [Bb*UEe];
__device__ float d_uq [Bb*Dd];
__device__ float d_sh [Bb*Dd];
__device__ float d_lg [Bb*Dd];

// ---------------- helpers ----------------
__device__ __forceinline__ float sigf(float x){ return __fdividef(1.f, 1.f + __expf(-x)); }
__device__ __forceinline__ float tanh_f(float x){ return 1.f - __fdividef(2.f, __expf(2.f*x) + 1.f); }
__device__ __forceinline__ float wredsum(float v){
  #pragma unroll
  for(int o=16;o;o>>=1) v += __shfl_xor_sync(0xffffffffu, v, o);
  return v;
}
__device__ __forceinline__ float wredmax(float v){
  #pragma unroll
  for(int o=16;o;o>>=1) v = fmaxf(v, __shfl_xor_sync(0xffffffffu, v, o));
  return v;
}

// ---------------- embedding gathers ----------------
__global__ __launch_bounds__(128) void embed_short_k(const int* __restrict__ sids,
    const float* __restrict__ emb, float* __restrict__ st0){
  int bs = blockIdx.x;            // b*S + s
  int d  = threadIdx.x;           // 0..127
  int f = d >> 5, e = d & 31;
  int id = sids[bs*Ff + f];
  st0[bs*Dd + d] = emb[id*Ee + e];
}

__global__ __launch_bounds__(256) void embed_user_k(const int* __restrict__ up,
    const float* __restrict__ emb, float* __restrict__ ue){
  int b = blockIdx.x;
  int t = threadIdx.x;            // 0..255
  int u = t >> 5, e = t & 31;
  ue[b*UEe + t] = emb[up[b*8 + u]*Ee + e];
}

// ---------------- generic fp32 tiled GEMM: C = A(MxK) @ B(KxN) (+bias[N]) ----------------
template<int BM,int BN,int TM,int TN>
__global__ __launch_bounds__(256) void gemm_k(const float* __restrict__ A,
    const float* __restrict__ B, const float* __restrict__ bias,
    float* __restrict__ C, int M, int N, int K)
{
  constexpr int BK = 16;
  __shared__ float As[BK][BM];    // transposed A tile
  __shared__ float Bs[BK][BN];
  const int tid  = threadIdx.x;
  const int row0 = blockIdx.y*BM, col0 = blockIdx.x*BN;
  const int tx = tid & 15, ty = tid >> 4;   // 16x16 thread grid
  float acc[TM][TN];
  #pragma unroll
  for(int i=0;i<TM;i++)
    #pragma unroll
    for(int j=0;j<TN;j++) acc[i][j]=0.f;

  for(int k0=0;k0<K;k0+=BK){
    #pragma unroll
    for(int i=0;i<(BM*BK)/1024;i++){
      int idx=(tid+i*256)*4;
      int r=idx>>4, c=idx&15;     // BK==16
      float4 va = *(const float4*)(A + (size_t)(row0+r)*K + k0 + c);
      As[c+0][r]=va.x; As[c+1][r]=va.y; As[c+2][r]=va.z; As[c+3][r]=va.w;
    }
    #pragma unroll
    for(int i=0;i<(BN*BK)/1024;i++){
      int idx=(tid+i*256)*4;
      int r=idx/BN, c=idx%BN;
      *(float4*)(&Bs[r][c]) = *(const float4*)(B + (size_t)(k0+r)*N + col0 + c);
    }
    __syncthreads();
    #pragma unroll
    for(int kk=0;kk<BK;kk++){
      float a[TM], b[TN];
      #pragma unroll
      for(int i=0;i<TM;i+=4) *(float4*)(a+i) = *(const float4*)(&As[kk][ty*TM+i]);
      #pragma unroll
      for(int j=0;j<TN;j+=4) *(float4*)(b+j) = *(const float4*)(&Bs[kk][tx*TN+j]);
      #pragma unroll
      for(int i=0;i<TM;i++)
        #pragma unroll
        for(int j=0;j<TN;j++) acc[i][j] += a[i]*b[j];
    }
    __syncthreads();
  }
  #pragma unroll
  for(int i=0;i<TM;i++){
    int r = row0 + ty*TM + i;
    #pragma unroll
    for(int j=0;j<TN;j+=4){
      int c = col0 + tx*TN + j;
      float4 v;
      v.x=acc[i][j]; v.y=acc[i][j+1]; v.z=acc[i][j+2]; v.w=acc[i][j+3];
      if(bias){ v.x+=bias[c]; v.y+=bias[c+1]; v.z+=bias[c+2]; v.w+=bias[c+3]; }
      *(float4*)(C + (size_t)r*N + c) = v;
    }
  }
}

// ---------------- LSTM recurrence (block-local over 8 batch rows) ----------------
__global__ __launch_bounds__(512) void lstm_k(const float* __restrict__ X,   // (B,S,512)
    const float* __restrict__ U,                                             // (128,512)
    float* __restrict__ hs)                                                  // (B,S,128)
{
  __shared__ float h[8][128];
  __shared__ float z[8][512];
  const int tid = threadIdx.x;        // 0..511 = output column
  const int b0  = blockIdx.x*8;
  for(int i=tid;i<8*128;i+=512) ((float*)h)[i]=0.f;
  float c0=0.f, c1=0.f;
  __syncthreads();

  for(int t=0;t<Ss;t++){
    float acc[8];
    #pragma unroll
    for(int r=0;r<8;r++) acc[r] = X[((size_t)(b0+r)*Ss + t)*512 + tid];
    #pragma unroll 4
    for(int k=0;k<128;k+=4){
      float u0=U[(k+0)*512+tid], u1=U[(k+1)*512+tid];
      float u2=U[(k+2)*512+tid], u3=U[(k+3)*512+tid];
      #pragma unroll
      for(int r=0;r<8;r++){
        float4 hv = *(const float4*)&h[r][k];
        acc[r] += hv.x*u0 + hv.y*u1 + hv.z*u2 + hv.w*u3;
      }
    }
    #pragma unroll
    for(int r=0;r<8;r++) z[r][tid]=acc[r];
    __syncthreads();
    #pragma unroll
    for(int p=0;p<2;p++){
      int idx = tid + p*512;
      int r = idx >> 7, j = idx & 127;
      float zi=z[r][j], zf=z[r][128+j], zg=z[r][256+j], zo=z[r][384+j];
      float c = p ? c1 : c0;
      c = sigf(zf)*c + sigf(zi)*tanh_f(zg);
      float hv = sigf(zo)*tanh_f(c);
      if(p) c1=c; else c0=c;
      h[r][j]=hv;
      hs[((size_t)(b0+r)*Ss + t)*Dd + j] = hv;
    }
    __syncthreads();
  }
}

// ---------------- MHA core (per (b,head) block) ----------------
__global__ __launch_bounds__(256) void mha_attn_k(const float* __restrict__ q,
    const float* __restrict__ k, const float* __restrict__ v, float* __restrict__ o)
{
  __shared__ float qs[Ss][33], ks[Ss][33], vs[Ss][33];
  __shared__ float sc[Ss][Ss];
  const int bh = blockIdx.x;
  const int b = bh >> 2, h = bh & 3;
  const int tid = threadIdx.x;
  const int warp = tid >> 5, lane = tid & 31;
  const float scale = 0.17677669529663687f;   // 1/sqrt(32)

  for(int i=tid;i<Ss*Ee;i+=256){
    int s=i>>5, e=i&31;
    size_t g = ((size_t)b*Ss+s)*Dd + h*Ee + e;
    qs[s][e]=q[g]; ks[s][e]=k[g]; vs[s][e]=v[g];
  }
  __syncthreads();
  for(int i=tid;i<Ss*Ss;i+=256){
    int a=i/Ss, c=i%Ss;
    float s=0.f;
    #pragma unroll
    for(int e=0;e<Ee;e++) s += qs[a][e]*ks[c][e];
    sc[a][c] = s*scale;
  }
  __syncthreads();
  for(int a=warp;a<Ss;a+=8){
    float m=-1e30f;
    for(int c=lane;c<Ss;c+=32) m=fmaxf(m,sc[a][c]);
    m=wredmax(m);
    float sum=0.f;
    for(int c=lane;c<Ss;c+=32){ float e_=__expf(sc[a][c]-m); sc[a][c]=e_; sum+=e_; }
    sum=wredsum(sum);
    float inv=__fdividef(1.f,sum);
    for(int c=lane;c<Ss;c+=32) sc[a][c]*=inv;
  }
  __syncthreads();
  for(int i=tid;i<Ss*Ee;i+=256){
    int a=i>>5, e=i&31;
    float s=0.f;
    #pragma unroll 10
    for(int c=0;c<Ss;c++) s += sc[a][c]*vs[c][e];
    o[((size_t)b*Ss+a)*Dd + h*Ee + e]=s;
  }
}

// ---------------- user-query attention over S -> short vector ----------------
__global__ __launch_bounds__(128) void user_attn_k(const float* __restrict__ st,
    const float* __restrict__ uq, float* __restrict__ shrt)
{
  __shared__ float qv[Dd];
  __shared__ float sc[64];
  const int b=blockIdx.x, tid=threadIdx.x;
  const int warp=tid>>5, lane=tid&31;
  qv[tid]=uq[b*Dd+tid];
  __syncthreads();
  for(int s=warp;s<Ss;s+=4){
    const float* row = st + ((size_t)b*Ss+s)*Dd;
    float p = row[lane]*qv[lane] + row[lane+32]*qv[lane+32]
            + row[lane+64]*qv[lane+64] + row[lane+96]*qv[lane+96];
    p=wredsum(p);
    if(lane==0) sc[s]=p;
  }
  __syncthreads();
  if(warp==0){
    float m=-1e30f;
    for(int s=lane;s<Ss;s+=32) m=fmaxf(m,sc[s]);
    m=wredmax(m);
    float sum=0.f;
    for(int s=lane;s<Ss;s+=32){ float e_=__expf(sc[s]-m); sc[s]=e_; sum+=e_; }
    sum=wredsum(sum);
    float inv=__fdividef(1.f,sum);
    for(int s=lane;s<Ss;s+=32) sc[s]*=inv;
  }
  __syncthreads();
  float acc=0.f;
  for(int s=0;s<Ss;s++) acc += sc[s]*st[((size_t)b*Ss+s)*Dd + tid];
  shrt[b*Dd+tid]=acc;
}

// ---------------- long-term field attention (per (b,field) block) ----------------
__global__ __launch_bounds__(256) void longterm_k(const int* __restrict__ lids,
    const float* __restrict__ emb, const float* __restrict__ ue,
    const float* __restrict__ Wt, const float* __restrict__ bt,
    float* __restrict__ lng)
{
  __shared__ int   ids[Ll];
  __shared__ int   keep[Ll];
  __shared__ float vec[Ll][33];
  __shared__ float uv[Ee];
  __shared__ float sc[Ll];
  __shared__ float pred[8][33];
  __shared__ float red[8];
  __shared__ float smax, ssum;

  const int bx=blockIdx.x;
  const int b=bx>>2, fi=bx&3;
  const int tid=threadIdx.x;
  const int warp=tid>>5, lane=tid&31;

  for(int l=tid;l<Ll;l+=256) ids[l]=lids[((size_t)b*Ll+l)*Ff + fi];
  __syncthreads();
  for(int l=tid;l<Ll;l+=256){
    int id=ids[l]; int kp=1;
    for(int j=0;j<l;j++) if(ids[j]==id){ kp=0; break; }
    keep[l]=kp;
  }
  for(int i=tid;i<Ll*Ee;i+=256){ int l=i>>5, e=i&31; vec[l][e]=emb[ids[l]*Ee+e]; }
  {
    int e=tid&31, kc=tid>>5;
    const float* wt = Wt + fi*UEe*Ee;
    float p=0.f;
    for(int kk=kc*32;kk<kc*32+32;kk++) p += ue[b*UEe+kk]*wt[kk*Ee+e];
    pred[kc][e]=p;
  }
  __syncthreads();
  if(tid<Ee){
    float s=bt[fi*Ee+tid];
    #pragma unroll
    for(int kc=0;kc<8;kc++) s+=pred[kc][tid];
    uv[tid]=s;
  }
  __syncthreads();
  for(int l=tid;l<Ll;l+=256){
    float s=0.f;
    #pragma unroll
    for(int e=0;e<Ee;e++) s+=vec[l][e]*uv[e];
    sc[l] = keep[l] ? s : NEGV;
  }
  __syncthreads();
  // block softmax over 200
  float m=-1e30f;
  for(int l=tid;l<Ll;l+=256) m=fmaxf(m,sc[l]);
  m=wredmax(m);
  if(lane==0) red[warp]=m;
  __syncthreads();
  if(tid==0){ float mm=red[0]; for(int w=1;w<8;w++) mm=fmaxf(mm,red[w]); smax=mm; }
  __syncthreads();
  float M=smax, ps=0.f;
  for(int l=tid;l<Ll;l+=256){ float e_=__expf(sc[l]-M); sc[l]=e_; ps+=e_; }
  ps=wredsum(ps);
  if(lane==0) red[warp]=ps;
  __syncthreads();
  if(tid==0){ float ss=0.f; for(int w=0;w<8;w++) ss+=red[w]; ssum=ss; }
  __syncthreads();
  float inv=__fdividef(1.f,ssum);
  // weighted sum
  {
    int e=tid&31, lc=tid>>5;
    float p=0.f;
    for(int l=lc*25;l<lc*25+25;l++) p += sc[l]*vec[l][e];
    pred[lc][e]=p;
  }
  __syncthreads();
  if(tid<Ee){
    float s=0.f;
    #pragma unroll
    for(int c=0;c<8;c++) s+=pred[c][tid];
    lng[b*Dd + fi*Ee + tid] = s*inv;
  }
}

// ---------------- gated fusion ----------------
__global__ __launch_bounds__(128) void gate_k(const float* __restrict__ ue,
    const float* __restrict__ sh, const float* __restrict__ lg,
    const float* __restrict__ Wu, const float* __restrict__ bu,
    const float* __restrict__ Wsg, const float* __restrict__ bsg,
    const float* __restrict__ Wl, const float* __restrict__ bl,
    float* __restrict__ out)
{
  __shared__ float sue[UEe], ssh[Dd], slg[Dd];
  const int b=blockIdx.x, tid=threadIdx.x;
  ssh[tid]=sh[b*Dd+tid];
  slg[tid]=lg[b*Dd+tid];
  sue[tid]=ue[b*UEe+tid];
  sue[tid+128]=ue[b*UEe+128+tid];
  __syncthreads();
  float acc = bu[tid]+bsg[tid]+bl[tid];
  #pragma unroll 4
  for(int kk=0;kk<UEe;kk++) acc += sue[kk]*Wu[kk*Dd+tid];
  #pragma unroll 4
  for(int kk=0;kk<Dd;kk++)  acc += ssh[kk]*Wsg[kk*Dd+tid];
  #pragma unroll 4
  for(int kk=0;kk<Dd;kk++)  acc += slg[kk]*Wl[kk*Dd+tid];
  float g = sigf(acc);
  out[b*Dd+tid] = (1.f-g)*slg[tid] + g*ssh[tid];
}

// ---------------- host glue ----------------
static float* symaddr(const void* sym){
  void* p=nullptr;
  cudaGetSymbolAddress(&p, sym);
  return (float*)p;
}

extern "C" void kernel_launch(void* const* d_in, const int* in_sizes, int n_in,
                              void* d_out, int out_size)
{
  const int*   up     = (const int*)  d_in[0];
  const int*   sids   = (const int*)  d_in[1];
  const int*   lids   = (const int*)  d_in[2];
  const float* emb    = (const float*)d_in[3];
  const float* lstm_W = (const float*)d_in[4];
  const float* lstm_U = (const float*)d_in[5];
  const float* lstm_b = (const float*)d_in[6];
  const float* Wq     = (const float*)d_in[7];
  const float* Wk     = (const float*)d_in[8];
  const float* Wv     = (const float*)d_in[9];
  const float* Wo     = (const float*)d_in[10];
  const float* W1     = (const float*)d_in[11];
  const float* b1     = (const float*)d_in[12];
  const float* Wt     = (const float*)d_in[13];
  const float* bt     = (const float*)d_in[14];
  const float* Wu     = (const float*)d_in[15];
  const float* bu     = (const float*)d_in[16];
  const float* Wsg    = (const float*)d_in[17];
  const float* bsg    = (const float*)d_in[18];
  const float* Wl     = (const float*)d_in[19];
  const float* bl     = (const float*)d_in[20];
  float* out = (float*)d_out;

  float* st0 = symaddr(d_st0);
  float* X   = symaddr(d_X);
  float* hs  = symaddr(d_hs);
  float* q   = symaddr(d_q);
  float* k   = symaddr(d_k);
  float* v   = symaddr(d_v);
  float* ao  = symaddr(d_ao);
  float* stm = symaddr(d_stm);
  float* ue  = symaddr(d_ue);
  float* uq  = symaddr(d_uq);
  float* sh  = symaddr(d_sh);
  float* lg  = symaddr(d_lg);

  const int MS = Bb*Ss;   // 51200

  embed_short_k<<<MS, 128>>>(sids, emb, st0);
  embed_user_k <<<Bb, 256>>>(up, emb, ue);

  // X = st0 @ lstm_W + lstm_b   (51200 x 512, K=128)
  gemm_k<128,128,8,8><<<dim3(512/128, MS/128), 256>>>(st0, lstm_W, lstm_b, X, MS, 512, Dd);

  // LSTM scan (block-local recurrence, 8 batch rows per block)
  lstm_k<<<Bb/8, 512>>>(X, lstm_U, hs);

  // Q/K/V projections (51200 x 128, K=128)
  gemm_k<128,128,8,8><<<dim3(1, MS/128), 256>>>(hs, Wq, nullptr, q, MS, Dd, Dd);
  gemm_k<128,128,8,8><<<dim3(1, MS/128), 256>>>(hs, Wk, nullptr, k, MS, Dd, Dd);
  gemm_k<128,128,8,8><<<dim3(1, MS/128), 256>>>(hs, Wv, nullptr, v, MS, Dd, Dd);

  mha_attn_k<<<Bb*Ff, 256>>>(q, k, v, ao);

  // output projection
  gemm_k<128,128,8,8><<<dim3(1, MS/128), 256>>>(ao, Wo, nullptr, stm, MS, Dd, Dd);

  // user query: uq = ue @ W1 + b1  (1024 x 128, K=256)
  gemm_k<64,64,4,4><<<dim3(Dd/64, Bb/64), 256>>>(ue, W1, b1, uq, Bb, Dd, UEe);

  user_attn_k<<<Bb, 128>>>(stm, uq, sh);

  longterm_k<<<Bb*Ff, 256>>>(lids, emb, ue, Wt, bt, lg);

  gate_k<<<Bb, 128>>>(ue, sh, lg, Wu, bu, Wsg, bsg, Wl, bl, out);
}

// round 5
// speedup vs baseline: 1.3431x; 1.3431x over previous
#include <cuda_runtime.h>
#include <math.h>

// Problem dims
#define Bb   1024
#define Ss   50
#define Ll   200
#define Ff   4
#define Ee   32
#define Dd   128     // F*E
#define UEe  256     // U*E
#define NEGV -1000000000.0f

// ---------------- scratch (static __device__, no allocation) ----------------
__device__ float d_st0[Bb*Ss*Dd];     // embedded short-term
__device__ float d_X  [Bb*Ss*4*Dd];   // precomputed x@W + b  (B,S,512)
__device__ float d_hs [Bb*Ss*Dd];     // lstm outputs
__device__ float d_q  [Bb*Ss*Dd];
__device__ float d_k  [Bb*Ss*Dd];
__device__ float d_v  [Bb*Ss*Dd];
__device__ float d_ao [Bb*Ss*Dd];     // attention out (pre-Wo)
__device__ float d_stm[Bb*Ss*Dd];     // mha output
__device__ float d_ue [Bb*UEe];
__device__ float d_uq [Bb*Dd];
__device__ float d_sh [Bb*Dd];
__device__ float d_lg [Bb*Dd];

// ---------------- helpers ----------------
__device__ __forceinline__ float sigf(float x){ return __fdividef(1.f, 1.f + __expf(-x)); }
__device__ __forceinline__ float tanh_f(float x){ return 1.f - __fdividef(2.f, __expf(2.f*x) + 1.f); }
__device__ __forceinline__ float wredsum(float v){
  #pragma unroll
  for(int o=16;o;o>>=1) v += __shfl_xor_sync(0xffffffffu, v, o);
  return v;
}
__device__ __forceinline__ float wredmax(float v){
  #pragma unroll
  for(int o=16;o;o>>=1) v = fmaxf(v, __shfl_xor_sync(0xffffffffu, v, o));
  return v;
}
__device__ __forceinline__ unsigned f2tf(float f){
  unsigned u; asm("cvt.rna.tf32.f32 %0, %1;" : "=r"(u) : "f"(f)); return u;
}
__device__ __forceinline__ void mma_tf32(float c[4], const unsigned a[4], const unsigned b[2]){
  asm volatile("mma.sync.aligned.m16n8k8.row.col.f32.tf32.tf32.f32 "
    "{%0,%1,%2,%3}, {%4,%5,%6,%7}, {%8,%9}, {%0,%1,%2,%3};"
    : "+f"(c[0]),"+f"(c[1]),"+f"(c[2]),"+f"(c[3])
    : "r"(a[0]),"r"(a[1]),"r"(a[2]),"r"(a[3]), "r"(b[0]),"r"(b[1]));
}

// ---------------- embedding gathers ----------------
__global__ __launch_bounds__(128) void embed_short_k(const int* __restrict__ sids,
    const float* __restrict__ emb, float* __restrict__ st0){
  int bs = blockIdx.x;            // b*S + s
  int d  = threadIdx.x;           // 0..127
  int f = d >> 5, e = d & 31;
  int id = sids[bs*Ff + f];
  st0[bs*Dd + d] = emb[id*Ee + e];
}

__global__ __launch_bounds__(256) void embed_user_k(const int* __restrict__ up,
    const float* __restrict__ emb, float* __restrict__ ue){
  int b = blockIdx.x;
  int t = threadIdx.x;            // 0..255
  int u = t >> 5, e = t & 31;
  ue[b*UEe + t] = emb[up[b*8 + u]*Ee + e];
}

// ---------------- tf32 tensor-core GEMM: C = A(MxK) @ B(KxN) (+bias) ----------------
// BM=128, BN=128, BK=16, 256 threads = 8 warps in 4x2 grid; warp tile 32x64.
// Requires M%128==0, N%128==0, K%16==0.
__global__ __launch_bounds__(256) void gemm_tf32_k(const float* __restrict__ A,
    const float* __restrict__ B, const float* __restrict__ bias,
    float* __restrict__ C, int M, int N, int K)
{
  __shared__ unsigned As[16][136];   // [k][m], pad 8 -> conflict-free frag loads
  __shared__ unsigned Bs[16][136];   // [k][n]
  const int tid = threadIdx.x, wid = tid>>5, lane = tid&31;
  const int wm = wid>>1, wn = wid&1;
  const int row0 = blockIdx.y*128, col0 = blockIdx.x*128;
  const int lr = lane>>2, lc = lane&3;

  float c[2][8][4];
  #pragma unroll
  for(int i=0;i<2;i++)
    #pragma unroll
    for(int j=0;j<8;j++)
      #pragma unroll
      for(int t=0;t<4;t++) c[i][j][t]=0.f;

  for(int k0=0;k0<K;k0+=16){
    // load A tile 128x16 (transposed into As[k][m], tf32-converted)
    #pragma unroll
    for(int i=0;i<2;i++){
      int e = (tid + i*256)*4;
      int r = e>>4, kk = e&15;
      float4 v = *(const float4*)(A + (size_t)(row0+r)*K + k0 + kk);
      As[kk+0][r]=f2tf(v.x); As[kk+1][r]=f2tf(v.y);
      As[kk+2][r]=f2tf(v.z); As[kk+3][r]=f2tf(v.w);
    }
    // load B tile 16x128 into Bs[k][n]
    #pragma unroll
    for(int i=0;i<2;i++){
      int e = (tid + i*256)*4;
      int r = e>>7, cc = e&127;
      float4 v = *(const float4*)(B + (size_t)(k0+r)*N + col0 + cc);
      unsigned* p = &Bs[r][cc];
      p[0]=f2tf(v.x); p[1]=f2tf(v.y); p[2]=f2tf(v.z); p[3]=f2tf(v.w);
    }
    __syncthreads();
    #pragma unroll
    for(int ks=0;ks<16;ks+=8){
      unsigned a[2][4], b[8][2];
      #pragma unroll
      for(int mt=0;mt<2;mt++){
        int ar = wm*32 + mt*16 + lr;
        int ak = ks + lc;
        a[mt][0]=As[ak][ar];   a[mt][1]=As[ak][ar+8];
        a[mt][2]=As[ak+4][ar]; a[mt][3]=As[ak+4][ar+8];
      }
      #pragma unroll
      for(int nt=0;nt<8;nt++){
        int bn = wn*64 + nt*8 + lr;
        int bk = ks + lc;
        b[nt][0]=Bs[bk][bn]; b[nt][1]=Bs[bk+4][bn];
      }
      #pragma unroll
      for(int mt=0;mt<2;mt++)
        #pragma unroll
        for(int nt=0;nt<8;nt++) mma_tf32(c[mt][nt], a[mt], b[nt]);
    }
    __syncthreads();
  }
  // epilogue
  #pragma unroll
  for(int mt=0;mt<2;mt++){
    #pragma unroll
    for(int nt=0;nt<8;nt++){
      int r  = row0 + wm*32 + mt*16 + lr;
      int cc = col0 + wn*64 + nt*8 + lc*2;
      float bx=0.f, by=0.f;
      if(bias){ bx=bias[cc]; by=bias[cc+1]; }
      float2 v0; v0.x=c[mt][nt][0]+bx; v0.y=c[mt][nt][1]+by;
      float2 v1; v1.x=c[mt][nt][2]+bx; v1.y=c[mt][nt][3]+by;
      *(float2*)(C + (size_t)r*N + cc)     = v0;
      *(float2*)(C + (size_t)(r+8)*N + cc) = v1;
    }
  }
}

// ---------------- small fp32 GEMM for user query (1024x128, K=256) ----------------
template<int BM,int BN,int TM,int TN>
__global__ __launch_bounds__(256) void gemm_k(const float* __restrict__ A,
    const float* __restrict__ B, const float* __restrict__ bias,
    float* __restrict__ C, int M, int N, int K)
{
  constexpr int BK = 16;
  __shared__ float As[BK][BM];
  __shared__ float Bs[BK][BN];
  const int tid  = threadIdx.x;
  const int row0 = blockIdx.y*BM, col0 = blockIdx.x*BN;
  const int tx = tid & 15, ty = tid >> 4;
  float acc[TM][TN];
  #pragma unroll
  for(int i=0;i<TM;i++)
    #pragma unroll
    for(int j=0;j<TN;j++) acc[i][j]=0.f;

  for(int k0=0;k0<K;k0+=BK){
    #pragma unroll
    for(int i=0;i<(BM*BK)/1024;i++){
      int idx=(tid+i*256)*4;
      int r=idx>>4, c=idx&15;
      float4 va = *(const float4*)(A + (size_t)(row0+r)*K + k0 + c);
      As[c+0][r]=va.x; As[c+1][r]=va.y; As[c+2][r]=va.z; As[c+3][r]=va.w;
    }
    #pragma unroll
    for(int i=0;i<(BN*BK)/1024;i++){
      int idx=(tid+i*256)*4;
      int r=idx/BN, c=idx%BN;
      *(float4*)(&Bs[r][c]) = *(const float4*)(B + (size_t)(k0+r)*N + col0 + c);
    }
    __syncthreads();
    #pragma unroll
    for(int kk=0;kk<BK;kk++){
      float a[TM], b[TN];
      #pragma unroll
      for(int i=0;i<TM;i+=4) *(float4*)(a+i) = *(const float4*)(&As[kk][ty*TM+i]);
      #pragma unroll
      for(int j=0;j<TN;j+=4) *(float4*)(b+j) = *(const float4*)(&Bs[kk][tx*TN+j]);
      #pragma unroll
      for(int i=0;i<TM;i++)
        #pragma unroll
        for(int j=0;j<TN;j++) acc[i][j] += a[i]*b[j];
    }
    __syncthreads();
  }
  #pragma unroll
  for(int i=0;i<TM;i++){
    int r = row0 + ty*TM + i;
    #pragma unroll
    for(int j=0;j<TN;j+=4){
      int c = col0 + tx*TN + j;
      float4 v;
      v.x=acc[i][j]; v.y=acc[i][j+1]; v.z=acc[i][j+2]; v.w=acc[i][j+3];
      if(bias){ v.x+=bias[c]; v.y+=bias[c+1]; v.z+=bias[c+2]; v.w+=bias[c+3]; }
      *(float4*)(C + (size_t)r*N + c) = v;
    }
  }
}

// ---------------- LSTM recurrence v2: 8 batch rows, 1024 threads, K split 2 ----------------
__global__ __launch_bounds__(1024) void lstm_k2(const float* __restrict__ X,  // (B,S,512)
    const float* __restrict__ U,                                              // (128,512)
    float* __restrict__ hs)                                                   // (B,S,128)
{
  __shared__ float h[8][128];
  __shared__ float z[2][8][512];
  const int tid = threadIdx.x;
  const int half = tid>>9;            // 0/1: k range [0,64) / [64,128)
  const int col  = tid & 511;         // output column 0..511
  const int b0   = blockIdx.x*8;
  const int gr = tid>>7 & 7, gj = tid & 127;   // gate-phase (row, j)
  const int kbase = half*64;

  h[tid>>7 & 7][tid & 127] = 0.f;     // 1024 threads cover 8x128 exactly
  float cst = 0.f;
  __syncthreads();

  for(int t=0;t<Ss;t++){
    float acc[8];
    if(half==0){
      #pragma unroll
      for(int r=0;r<8;r++) acc[r] = X[((size_t)(b0+r)*Ss + t)*512 + col];
    } else {
      #pragma unroll
      for(int r=0;r<8;r++) acc[r] = 0.f;
    }
    #pragma unroll
    for(int k=0;k<64;k+=8){
      float u[8];
      #pragma unroll
      for(int i=0;i<8;i++) u[i] = U[(size_t)(kbase+k+i)*512 + col];
      #pragma unroll
      for(int r=0;r<8;r++){
        float4 h0 = *(const float4*)&h[r][kbase+k];
        float4 h1 = *(const float4*)&h[r][kbase+k+4];
        acc[r] += h0.x*u[0] + h0.y*u[1] + h0.z*u[2] + h0.w*u[3]
                + h1.x*u[4] + h1.y*u[5] + h1.z*u[6] + h1.w*u[7];
      }
    }
    #pragma unroll
    for(int r=0;r<8;r++) z[half][r][col] = acc[r];
    __syncthreads();
    {
      float zi = z[0][gr][gj]     + z[1][gr][gj];
      float zf = z[0][gr][128+gj] + z[1][gr][128+gj];
      float zg = z[0][gr][256+gj] + z[1][gr][256+gj];
      float zo = z[0][gr][384+gj] + z[1][gr][384+gj];
      cst = sigf(zf)*cst + sigf(zi)*tanh_f(zg);
      float hv = sigf(zo)*tanh_f(cst);
      h[gr][gj] = hv;
      hs[((size_t)(b0+gr)*Ss + t)*Dd + gj] = hv;
    }
    __syncthreads();
  }
}

// ---------------- MHA core (per (b,head) block) ----------------
__global__ __launch_bounds__(256) void mha_attn_k(const float* __restrict__ q,
    const float* __restrict__ k, const float* __restrict__ v, float* __restrict__ o)
{
  __shared__ float qs[Ss][33], ks[Ss][33], vs[Ss][33];
  __shared__ float sc[Ss][Ss];
  const int bh = blockIdx.x;
  const int b = bh >> 2, h = bh & 3;
  const int tid = threadIdx.x;
  const int warp = tid >> 5, lane = tid & 31;
  const float scale = 0.17677669529663687f;   // 1/sqrt(32)

  for(int i=tid;i<Ss*Ee;i+=256){
    int s=i>>5, e=i&31;
    size_t g = ((size_t)b*Ss+s)*Dd + h*Ee + e;
    qs[s][e]=q[g]; ks[s][e]=k[g]; vs[s][e]=v[g];
  }
  __syncthreads();
  for(int i=tid;i<Ss*Ss;i+=256){
    int a=i/Ss, c=i%Ss;
    float s=0.f;
    #pragma unroll
    for(int e=0;e<Ee;e++) s += qs[a][e]*ks[c][e];
    sc[a][c] = s*scale;
  }
  __syncthreads();
  for(int a=warp;a<Ss;a+=8){
    float m=-1e30f;
    for(int c=lane;c<Ss;c+=32) m=fmaxf(m,sc[a][c]);
    m=wredmax(m);
    float sum=0.f;
    for(int c=lane;c<Ss;c+=32){ float e_=__expf(sc[a][c]-m); sc[a][c]=e_; sum+=e_; }
    sum=wredsum(sum);
    float inv=__fdividef(1.f,sum);
    for(int c=lane;c<Ss;c+=32) sc[a][c]*=inv;
  }
  __syncthreads();
  for(int i=tid;i<Ss*Ee;i+=256){
    int a=i>>5, e=i&31;
    float s=0.f;
    #pragma unroll 10
    for(int c=0;c<Ss;c++) s += sc[a][c]*vs[c][e];
    o[((size_t)b*Ss+a)*Dd + h*Ee + e]=s;
  }
}

// ---------------- user-query attention over S -> short vector ----------------
__global__ __launch_bounds__(128) void user_attn_k(const float* __restrict__ st,
    const float* __restrict__ uq, float* __restrict__ shrt)
{
  __shared__ float qv[Dd];
  __shared__ float sc[64];
  const int b=blockIdx.x, tid=threadIdx.x;
  const int warp=tid>>5, lane=tid&31;
  qv[tid]=uq[b*Dd+tid];
  __syncthreads();
  for(int s=warp;s<Ss;s+=4){
    const float* row = st + ((size_t)b*Ss+s)*Dd;
    float p = row[lane]*qv[lane] + row[lane+32]*qv[lane+32]
            + row[lane+64]*qv[lane+64] + row[lane+96]*qv[lane+96];
    p=wredsum(p);
    if(lane==0) sc[s]=p;
  }
  __syncthreads();
  if(warp==0){
    float m=-1e30f;
    for(int s=lane;s<Ss;s+=32) m=fmaxf(m,sc[s]);
    m=wredmax(m);
    float sum=0.f;
    for(int s=lane;s<Ss;s+=32){ float e_=__expf(sc[s]-m); sc[s]=e_; sum+=e_; }
    sum=wredsum(sum);
    float inv=__fdividef(1.f,sum);
    for(int s=lane;s<Ss;s+=32) sc[s]*=inv;
  }
  __syncthreads();
  float acc=0.f;
  for(int s=0;s<Ss;s++) acc += sc[s]*st[((size_t)b*Ss+s)*Dd + tid];
  shrt[b*Dd+tid]=acc;
}

// ---------------- long-term field attention (per (b,field) block) ----------------
__global__ __launch_bounds__(256) void longterm_k(const int* __restrict__ lids,
    const float* __restrict__ emb, const float* __restrict__ ue,
    const float* __restrict__ Wt, const float* __restrict__ bt,
    float* __restrict__ lng)
{
  __shared__ int   ids[Ll];
  __shared__ int   keep[Ll];
  __shared__ float vec[Ll][33];
  __shared__ float uv[Ee];
  __shared__ float sc[Ll];
  __shared__ float pred[8][33];
  __shared__ float red[8];
  __shared__ float smax, ssum;

  const int bx=blockIdx.x;
  const int b=bx>>2, fi=bx&3;
  const int tid=threadIdx.x;
  const int warp=tid>>5, lane=tid&31;

  for(int l=tid;l<Ll;l+=256) ids[l]=lids[((size_t)b*Ll+l)*Ff + fi];
  __syncthreads();
  for(int l=tid;l<Ll;l+=256){
    int id=ids[l]; int kp=1;
    for(int j=0;j<l;j++) if(ids[j]==id){ kp=0; break; }
    keep[l]=kp;
  }
  for(int i=tid;i<Ll*Ee;i+=256){ int l=i>>5, e=i&31; vec[l][e]=emb[ids[l]*Ee+e]; }
  {
    int e=tid&31, kc=tid>>5;
    const float* wt = Wt + fi*UEe*Ee;
    float p=0.f;
    for(int kk=kc*32;kk<kc*32+32;kk++) p += ue[b*UEe+kk]*wt[kk*Ee+e];
    pred[kc][e]=p;
  }
  __syncthreads();
  if(tid<Ee){
    float s=bt[fi*Ee+tid];
    #pragma unroll
    for(int kc=0;kc<8;kc++) s+=pred[kc][tid];
    uv[tid]=s;
  }
  __syncthreads();
  for(int l=tid;l<Ll;l+=256){
    float s=0.f;
    #pragma unroll
    for(int e=0;e<Ee;e++) s+=vec[l][e]*uv[e];
    sc[l] = keep[l] ? s : NEGV;
  }
  __syncthreads();
  float m=-1e30f;
  for(int l=tid;l<Ll;l+=256) m=fmaxf(m,sc[l]);
  m=wredmax(m);
  if(lane==0) red[warp]=m;
  __syncthreads();
  if(tid==0){ float mm=red[0]; for(int w=1;w<8;w++) mm=fmaxf(mm,red[w]); smax=mm; }
  __syncthreads();
  float M=smax, ps=0.f;
  for(int l=tid;l<Ll;l+=256){ float e_=__expf(sc[l]-M); sc[l]=e_; ps+=e_; }
  ps=wredsum(ps);
  if(lane==0) red[warp]=ps;
  __syncthreads();
  if(tid==0){ float ss=0.f; for(int w=0;w<8;w++) ss+=red[w]; ssum=ss; }
  __syncthreads();
  float inv=__fdividef(1.f,ssum);
  {
    int e=tid&31, lc=tid>>5;
    float p=0.f;
    for(int l=lc*25;l<lc*25+25;l++) p += sc[l]*vec[l][e];
    pred[lc][e]=p;
  }
  __syncthreads();
  if(tid<Ee){
    float s=0.f;
    #pragma unroll
    for(int c=0;c<8;c++) s+=pred[c][tid];
    lng[b*Dd + fi*Ee + tid] = s*inv;
  }
}

// ---------------- gated fusion ----------------
__global__ __launch_bounds__(128) void gate_k(const float* __restrict__ ue,
    const float* __restrict__ sh, const float* __restrict__ lg,
    const float* __restrict__ Wu, const float* __restrict__ bu,
    const float* __restrict__ Wsg, const float* __restrict__ bsg,
    const float* __restrict__ Wl, const float* __restrict__ bl,
    float* __restrict__ out)
{
  __shared__ float sue[UEe], ssh[Dd], slg[Dd];
  const int b=blockIdx.x, tid=threadIdx.x;
  ssh[tid]=sh[b*Dd+tid];
  slg[tid]=lg[b*Dd+tid];
  sue[tid]=ue[b*UEe+tid];
  sue[tid+128]=ue[b*UEe+128+tid];
  __syncthreads();
  float acc = bu[tid]+bsg[tid]+bl[tid];
  #pragma unroll 4
  for(int kk=0;kk<UEe;kk++) acc += sue[kk]*Wu[kk*Dd+tid];
  #pragma unroll 4
  for(int kk=0;kk<Dd;kk++)  acc += ssh[kk]*Wsg[kk*Dd+tid];
  #pragma unroll 4
  for(int kk=0;kk<Dd;kk++)  acc += slg[kk]*Wl[kk*Dd+tid];
  float g = sigf(acc);
  out[b*Dd+tid] = (1.f-g)*slg[tid] + g*ssh[tid];
}

// ---------------- host glue ----------------
static float* symaddr(const void* sym){
  void* p=nullptr;
  cudaGetSymbolAddress(&p, sym);
  return (float*)p;
}

extern "C" void kernel_launch(void* const* d_in, const int* in_sizes, int n_in,
                              void* d_out, int out_size)
{
  const int*   up     = (const int*)  d_in[0];
  const int*   sids   = (const int*)  d_in[1];
  const int*   lids   = (const int*)  d_in[2];
  const float* emb    = (const float*)d_in[3];
  const float* lstm_W = (const float*)d_in[4];
  const float* lstm_U = (const float*)d_in[5];
  const float* lstm_b = (const float*)d_in[6];
  const float* Wq     = (const float*)d_in[7];
  const float* Wk     = (const float*)d_in[8];
  const float* Wv     = (const float*)d_in[9];
  const float* Wo     = (const float*)d_in[10];
  const float* W1     = (const float*)d_in[11];
  const float* b1     = (const float*)d_in[12];
  const float* Wt     = (const float*)d_in[13];
  const float* bt     = (const float*)d_in[14];
  const float* Wu     = (const float*)d_in[15];
  const float* bu     = (const float*)d_in[16];
  const float* Wsg    = (const float*)d_in[17];
  const float* bsg    = (const float*)d_in[18];
  const float* Wl     = (const float*)d_in[19];
  const float* bl     = (const float*)d_in[20];
  float* out = (float*)d_out;

  float* st0 = symaddr(d_st0);
  float* X   = symaddr(d_X);
  float* hs  = symaddr(d_hs);
  float* q   = symaddr(d_q);
  float* k   = symaddr(d_k);
  float* v   = symaddr(d_v);
  float* ao  = symaddr(d_ao);
  float* stm = symaddr(d_stm);
  float* ue  = symaddr(d_ue);
  float* uq  = symaddr(d_uq);
  float* sh  = symaddr(d_sh);
  float* lg  = symaddr(d_lg);

  const int MS = Bb*Ss;   // 51200

  embed_short_k<<<MS, 128>>>(sids, emb, st0);
  embed_user_k <<<Bb, 256>>>(up, emb, ue);

  // X = st0 @ lstm_W + lstm_b   (51200 x 512, K=128) -- tf32 tensor cores
  gemm_tf32_k<<<dim3(512/128, MS/128), 256>>>(st0, lstm_W, lstm_b, X, MS, 512, Dd);

  // LSTM scan (block-local recurrence, 8 batch rows per block, 1024 threads)
  lstm_k2<<<Bb/8, 1024>>>(X, lstm_U, hs);

  // Q/K/V projections (51200 x 128, K=128) -- tf32
  gemm_tf32_k<<<dim3(1, MS/128), 256>>>(hs, Wq, nullptr, q, MS, Dd, Dd);
  gemm_tf32_k<<<dim3(1, MS/128), 256>>>(hs, Wk, nullptr, k, MS, Dd, Dd);
  gemm_tf32_k<<<dim3(1, MS/128), 256>>>(hs, Wv, nullptr, v, MS, Dd, Dd);

  mha_attn_k<<<Bb*Ff, 256>>>(q, k, v, ao);

  // output projection -- tf32
  gemm_tf32_k<<<dim3(1, MS/128), 256>>>(ao, Wo, nullptr, stm, MS, Dd, Dd);

  // user query: uq = ue @ W1 + b1  (1024 x 128, K=256) -- small, keep fp32
  gemm_k<64,64,4,4><<<dim3(Dd/64, Bb/64), 256>>>(ue, W1, b1, uq, Bb, Dd, UEe);

  user_attn_k<<<Bb, 128>>>(stm, uq, sh);

  longterm_k<<<Bb*Ff, 256>>>(lids, emb, ue, Wt, bt, lg);

  gate_k<<<Bb, 128>>>(ue, sh, lg, Wu, bu, Wsg, bsg, Wl, bl, out);
}